// round 17
// baseline (speedup 1.0000x reference)
#include <cuda_runtime.h>
#include <cuda_fp16.h>
#include <math.h>
#include <stdint.h>

// Problem constants (fixed shapes)
#define B    8
#define C    192
#define C2   384
#define NH   4
#define CH   48
#define H    128
#define WD   128
#define HW   16384
#define NCHUNK 16
#define CHUNK  1024

// ---------------- scratch (static __device__ arrays) ------------------------
__device__ __half g_t1 [B * C2 * HW];
__device__ __half g_kv [B * C2 * HW];
__device__ __half g_t2 [B * C  * HW];
__device__ __half g_q  [B * C  * HW];
__device__ float g_pS [B * NH * NCHUNK * CH * CH];
__device__ float g_pnq[B * NH * NCHUNK * CH];
__device__ float g_pnk[B * NH * NCHUNK * CH];
__device__ float g_attn[B * NH * CH * CH];
__device__ __half g_xta[(size_t)B * HW * 192];  // x, later attn output
__device__ __half g_xtb[(size_t)B * HW * 192];  // y
__device__ __half g_w1[384 * 192];
__device__ __half g_w2[192 * 192];
__device__ __half g_w3[192 * 192];

// ---------------- PTX helpers (sm_103 baseline ISA only) --------------------
__device__ __forceinline__ uint32_t smem_u32(const void* p) {
    uint32_t a;
    asm("{ .reg .u64 t; cvta.to.shared.u64 t, %1; cvt.u32.u64 %0, t; }"
        : "=r"(a) : "l"(p));
    return a;
}
#define CP16(d, s) \
    asm volatile("cp.async.cg.shared.global [%0], [%1], 16;" :: "r"(d), "l"(s))
#define CP_COMMIT() asm volatile("cp.async.commit_group;")
#define CP_WAIT(n)  asm volatile("cp.async.wait_group %0;" :: "n"(n))

// NON-volatile: let ptxas schedule/pipeline LDSM against MMA.
__device__ __forceinline__ void ldm4(uint32_t* r, uint32_t addr) {
    asm("ldmatrix.sync.aligned.m8n8.x4.shared.b16 {%0,%1,%2,%3}, [%4];"
        : "=r"(r[0]), "=r"(r[1]), "=r"(r[2]), "=r"(r[3]) : "r"(addr));
}
__device__ __forceinline__ void mma_f16(float* c, const uint32_t* a,
                                        const uint32_t* b) {
    asm("mma.sync.aligned.m16n8k16.row.col.f32.f16.f16.f32 "
        "{%0,%1,%2,%3}, {%4,%5,%6,%7}, {%8,%9}, {%0,%1,%2,%3};"
        : "+f"(c[0]), "+f"(c[1]), "+f"(c[2]), "+f"(c[3])
        : "r"(a[0]), "r"(a[1]), "r"(a[2]), "r"(a[3]), "r"(b[0]), "r"(b[1]));
}

// ---------------- weight convert: W[Cout][192] fp32 -> fp16 ------------------
__global__ void prep_w_kernel(const float* __restrict__ w,
                              __half* __restrict__ o) {
    int m = blockIdx.x;
    int k = threadIdx.x;
    o[(size_t)m * 192 + k] = __float2half(w[(size_t)m * 192 + k]);
}

// ---------------- activation fp16 transpose: [B,192,HW] -> [B,HW,192] -------
__global__ __launch_bounds__(256) void split_transpose_kernel(
    const float* __restrict__ in, __half* __restrict__ out)
{
    const int n0 = blockIdx.x * 64;
    const int b  = blockIdx.y;
    __shared__ __half sT[64][198];

    const float* ip = in + (size_t)b * 192 * HW + n0;
    const int nn = threadIdx.x & 63;
    const int kq = threadIdx.x >> 6;

    for (int k0 = 0; k0 < 192; k0 += 8) {
        int k = k0 + kq * 2;
        float v0 = ip[(size_t)k * HW + nn];
        float v1 = ip[(size_t)(k + 1) * HW + nn];
        *(__half2*)(&sT[nn][k]) = __half2(__float2half(v0), __float2half(v1));
    }
    __syncthreads();

    uint32_t* op = (uint32_t*)(out + ((size_t)b * HW + n0) * 192);
    for (int idx = threadIdx.x; idx < 64 * 96; idx += 256) {
        int r = idx / 96, u = idx - r * 96;
        op[(size_t)r * 96 + u] = *(const uint32_t*)(&sT[r][u * 2]);
    }
}

// ---------------- HMMA GEMM, resident weights, frag-pipelined ----------------
// 256 threads (8 warps: 2 pixel halves x 4 cout quarters). Weights 192x192
// staged once; T=4 pixel tiles of 128, A double-buffered (dist-1 prefetch);
// fragments double-buffered across the 12 ks-halves.
#define WPITCH  400
#define W_BYTES (192 * WPITCH)        // 76800
#define A_BYTES (128 * WPITCH)        // 51200
#define SM_W    0
#define SM_A    W_BYTES
#define GSM_TOTAL (W_BYTES + 2 * A_BYTES)  // 179200
#define TPT     4

__device__ __forceinline__ void load_W(uint32_t sw, const char* wsrc, int tid) {
    for (int idx = tid; idx < 192 * 24; idx += 256) {
        int row = idx / 24, q = idx - row * 24;
        CP16(sw + row * WPITCH + q * 16, wsrc + (size_t)row * 384 + q * 16);
    }
    CP_COMMIT();
}
__device__ __forceinline__ void load_A(uint32_t sa, const char* asrc, int tid) {
    for (int idx = tid; idx < 128 * 24; idx += 256) {
        int row = idx / 24, q = idx - row * 24;
        CP16(sa + row * WPITCH + q * 16, asrc + (size_t)row * 384 + q * 16);
    }
    CP_COMMIT();
}

__device__ __forceinline__ void load_frags(
    uint32_t sa, uint32_t sw, int u, int lane, int wy, int wx,
    uint32_t af[4][4], uint32_t bf[3][4])
{
    const uint32_t acol = (u >> 1) * 64 + (u & 1) * 32 + (lane >> 4) * 16;
    const uint32_t bcol = (u >> 1) * 64 + (u & 1) * 32 + ((lane >> 3) & 1) * 16;
#pragma unroll
    for (int mi = 0; mi < 4; mi++)
        ldm4(af[mi], sa + (wy * 64 + mi * 16 + (lane & 15)) * WPITCH + acol);
#pragma unroll
    for (int nj = 0; nj < 3; nj++)
        ldm4(bf[nj], sw + (wx * 48 + nj * 16 + (lane & 7)
                           + (lane >> 4) * 8) * WPITCH + bcol);
}

__device__ __forceinline__ void gemm_body(
    const __half* xt, const __half* wsp, void* outv,
    int Cout, int fp16out, int pix0, int cout0, int b,
    uint32_t sb, int tid)
{
    const int lane = tid & 31, wid = tid >> 5;
    const int wy = wid >> 2;            // pixel half (64 each)
    const int wx = wid & 3;             // cout quarter (48 each)

    const char* abase = (const char*)(xt + ((size_t)(b * HW) + pix0) * 192);
    const char* wbase = (const char*)(wsp + (size_t)cout0 * 192);

    load_W(sb + SM_W, wbase, tid);
    load_A(sb + SM_A, abase, tid);

    const int prow = lane >> 2;
    const int ccol = (lane & 3) * 2;
    const uint32_t sw = sb + SM_W;

    for (int t = 0; t < TPT; t++) {
        if (t + 1 < TPT) {
            load_A(sb + SM_A + ((t + 1) & 1) * A_BYTES,
                   abase + (size_t)(t + 1) * 128 * 384, tid);
            CP_WAIT(1);
        } else {
            CP_WAIT(0);
        }
        __syncthreads();

        const uint32_t sa = sb + SM_A + (t & 1) * A_BYTES;

        float acc[4][6][4];
#pragma unroll
        for (int i = 0; i < 4; i++)
#pragma unroll
            for (int j = 0; j < 6; j++)
#pragma unroll
                for (int u = 0; u < 4; u++) acc[i][j][u] = 0.0f;

        uint32_t af[2][4][4], bf[2][3][4];
        load_frags(sa, sw, 0, lane, wy, wx, af[0], bf[0]);
#pragma unroll
        for (int u = 0; u < 12; u++) {
            const int cur = u & 1, nxt = cur ^ 1;
            if (u + 1 < 12)
                load_frags(sa, sw, u + 1, lane, wy, wx, af[nxt], bf[nxt]);
#pragma unroll
            for (int mi = 0; mi < 4; mi++)
#pragma unroll
                for (int nj = 0; nj < 3; nj++) {
                    mma_f16(acc[mi][nj * 2],     af[cur][mi], &bf[cur][nj][0]);
                    mma_f16(acc[mi][nj * 2 + 1], af[cur][mi], &bf[cur][nj][2]);
                }
        }

        const int ptile = pix0 + t * 128;
        if (fp16out) {
            __half* oh = (__half*)outv;
#pragma unroll
            for (int mi = 0; mi < 4; mi++) {
                const int p = ptile + wy * 64 + mi * 16 + prow;
#pragma unroll
                for (int ni = 0; ni < 6; ni++) {
                    const int co = cout0 + wx * 48 + ni * 8 + ccol;
                    __half* o0 = oh + ((size_t)b * Cout + co) * HW + p;
                    o0[0]      = __float2half(acc[mi][ni][0]);
                    o0[HW]     = __float2half(acc[mi][ni][1]);
                    o0[8]      = __float2half(acc[mi][ni][2]);
                    o0[HW + 8] = __float2half(acc[mi][ni][3]);
                }
            }
        } else {
            float* of = (float*)outv;
#pragma unroll
            for (int mi = 0; mi < 4; mi++) {
                const int p = ptile + wy * 64 + mi * 16 + prow;
#pragma unroll
                for (int ni = 0; ni < 6; ni++) {
                    const int co = cout0 + wx * 48 + ni * 8 + ccol;
                    float* o0 = of + ((size_t)b * Cout + co) * HW + p;
                    o0[0]      = acc[mi][ni][0];
                    o0[HW]     = acc[mi][ni][1];
                    o0[8]      = acc[mi][ni][2];
                    o0[HW + 8] = acc[mi][ni][3];
                }
            }
        }
        __syncthreads();
    }
}

// merged conv1+conv2: grid.y 0,1 -> conv1 cout block y; y==2 -> conv2
__global__ __launch_bounds__(256, 1) void gemm12_kernel()
{
    extern __shared__ char smem[];
    const uint32_t sb = smem_u32(smem);
    const int pix0 = blockIdx.x * (TPT * 128);
    const int b    = blockIdx.z;
    if (blockIdx.y < 2)
        gemm_body(g_xta, g_w1, g_t1, 384, 1, pix0, blockIdx.y * 192, b,
                  sb, threadIdx.x);
    else
        gemm_body(g_xtb, g_w2, g_t2, 192, 1, pix0, 0, b, sb, threadIdx.x);
}

__global__ __launch_bounds__(256, 1) void gemm3_kernel(float* __restrict__ out)
{
    extern __shared__ char smem[];
    const uint32_t sb = smem_u32(smem);
    gemm_body(g_xta, g_w3, out, 192, 0, blockIdx.x * (TPT * 128), 0,
              blockIdx.z, sb, threadIdx.x);
}

// ---------------- depthwise 3x3, SAME padding, fp16 in/out -------------------
__global__ __launch_bounds__(128) void dwconv3x3_kernel(
    const __half* __restrict__ in, const float* __restrict__ w9,
    __half* __restrict__ out, int Cc)
{
    const int y0 = blockIdx.x * 8;
    const int c  = blockIdx.y;
    const int b  = blockIdx.z;
    const int x  = threadIdx.x;

    __shared__ float s[10][130];
    const __half* ip = in  + ((size_t)b * Cc + c) * HW;
    __half*       op = out + ((size_t)b * Cc + c) * HW;

    float wr[9];
#pragma unroll
    for (int t = 0; t < 9; t++) wr[t] = w9[c * 9 + t];

#pragma unroll
    for (int r = 0; r < 10; r++) {
        int yy = y0 - 1 + r;
        s[r][x + 1] = (yy >= 0 && yy < H) ? __half2float(ip[yy * WD + x]) : 0.0f;
    }
    if (x == 0) {
#pragma unroll
        for (int r = 0; r < 10; r++) { s[r][0] = 0.0f; s[r][129] = 0.0f; }
    }
    __syncthreads();

#pragma unroll
    for (int ry = 0; ry < 8; ry++) {
        float a =
            s[ry + 0][x + 0] * wr[0] + s[ry + 0][x + 1] * wr[1] + s[ry + 0][x + 2] * wr[2] +
            s[ry + 1][x + 0] * wr[3] + s[ry + 1][x + 1] * wr[4] + s[ry + 1][x + 2] * wr[5] +
            s[ry + 2][x + 0] * wr[6] + s[ry + 2][x + 1] * wr[7] + s[ry + 2][x + 2] * wr[8];
        op[(y0 + ry) * WD + x] = __float2half(a);
    }
}

// ---------------- split-K Gram + norms (fp16 inputs) --------------------------
__global__ __launch_bounds__(256) void gram_kernel()
{
    const int ck = blockIdx.x, h = blockIdx.y, b = blockIdx.z;
    const int tid = threadIdx.x;
    const int tx = tid & 15, ty = tid >> 4;

    const __half* qp = g_q  + ((size_t)b * C  + h * CH) * HW + ck * CHUNK;
    const __half* kp = g_kv + ((size_t)b * C2 + h * CH) * HW + ck * CHUNK;

    __shared__ float sQ[32][49];
    __shared__ float sK[32][49];

    float acc[3][3];
#pragma unroll
    for (int i = 0; i < 3; i++)
#pragma unroll
        for (int j = 0; j < 3; j++) acc[i][j] = 0.0f;
    float sq[3] = {0.f, 0.f, 0.f}, sk2[3] = {0.f, 0.f, 0.f};

    for (int nb = 0; nb < CHUNK; nb += 32) {
#pragma unroll
        for (int e = 0; e < 6; e++) {
            int idx = tid + e * 256;
            int cc = idx >> 5, nn = idx & 31;
            sQ[nn][cc] = __half2float(qp[(size_t)cc * HW + nb + nn]);
            sK[nn][cc] = __half2float(kp[(size_t)cc * HW + nb + nn]);
        }
        __syncthreads();
#pragma unroll
        for (int kk = 0; kk < 32; kk++) {
            float a0 = sQ[kk][ty * 3 + 0];
            float a1 = sQ[kk][ty * 3 + 1];
            float a2 = sQ[kk][ty * 3 + 2];
            float b0 = sK[kk][tx * 3 + 0];
            float b1 = sK[kk][tx * 3 + 1];
            float b2 = sK[kk][tx * 3 + 2];
            acc[0][0] += a0 * b0; acc[0][1] += a0 * b1; acc[0][2] += a0 * b2;
            acc[1][0] += a1 * b0; acc[1][1] += a1 * b1; acc[1][2] += a1 * b2;
            acc[2][0] += a2 * b0; acc[2][1] += a2 * b1; acc[2][2] += a2 * b2;
            if (tx == 0) { sq[0]  += a0 * a0; sq[1]  += a1 * a1; sq[2]  += a2 * a2; }
            if (ty == 0) { sk2[0] += b0 * b0; sk2[1] += b1 * b1; sk2[2] += b2 * b2; }
        }
        __syncthreads();
    }

    const int base = (b * NH + h) * NCHUNK + ck;
    float* ps = g_pS + (size_t)base * (CH * CH);
#pragma unroll
    for (int i = 0; i < 3; i++)
#pragma unroll
        for (int j = 0; j < 3; j++)
            ps[(ty * 3 + i) * CH + tx * 3 + j] = acc[i][j];
    if (tx == 0) {
#pragma unroll
        for (int i = 0; i < 3; i++) g_pnq[base * CH + ty * 3 + i] = sq[i];
    }
    if (ty == 0) {
#pragma unroll
        for (int j = 0; j < 3; j++) g_pnk[base * CH + tx * 3 + j] = sk2[j];
    }
}

// ---------------- reduce, normalize, temperature, softmax --------------------
__global__ __launch_bounds__(256) void reduce_softmax_kernel(
    const float* __restrict__ temperature)
{
    const int bh = blockIdx.x;
    const int h  = bh & (NH - 1);
    const int tid = threadIdx.x;

    __shared__ float sS[CH * CH];
    __shared__ float snq[CH], snk[CH];

    for (int idx = tid; idx < CH * CH; idx += 256) {
        float s = 0.0f;
        for (int ck = 0; ck < NCHUNK; ck++)
            s += g_pS[(size_t)(bh * NCHUNK + ck) * (CH * CH) + idx];
        sS[idx] = s;
    }
    if (tid < CH) {
        float s = 0.0f;
        for (int ck = 0; ck < NCHUNK; ck++)
            s += g_pnq[(bh * NCHUNK + ck) * CH + tid];
        snq[tid] = fmaxf(sqrtf(s), 1e-12f);
    } else if (tid >= 64 && tid < 64 + CH) {
        int d = tid - 64;
        float s = 0.0f;
        for (int ck = 0; ck < NCHUNK; ck++)
            s += g_pnk[(bh * NCHUNK + ck) * CH + d];
        snk[d] = fmaxf(sqrtf(s), 1e-12f);
    }
    __syncthreads();

    const float t = temperature[h];
    for (int idx = tid; idx < CH * CH; idx += 256) {
        int cc = idx / CH, d = idx - cc * CH;
        sS[idx] = sS[idx] * t / (snq[cc] * snk[d]);
    }
    __syncthreads();

    if (tid < CH) {
        const int cc = tid;
        float m = -1e30f;
        for (int d = 0; d < CH; d++) m = fmaxf(m, sS[cc * CH + d]);
        float sum = 0.0f;
        for (int d = 0; d < CH; d++) {
            float e = expf(sS[cc * CH + d] - m);
            sS[cc * CH + d] = e;
            sum += e;
        }
        float inv = 1.0f / sum;
        for (int d = 0; d < CH; d++)
            g_attn[(size_t)bh * (CH * CH) + cc * CH + d] = sS[cc * CH + d] * inv;
    }
}

// ---------------- attn@v (fp16 V) fused with fp16 transpose -------------------
__global__ __launch_bounds__(256) void attnv_split_kernel()
{
    const int n0 = blockIdx.x * 128;
    const int h  = blockIdx.y, b = blockIdx.z;
    const int tid = threadIdx.x;
    const int tx = tid & 31, ty = tid >> 5;

    __shared__ float sA[CH][CH];
    __shared__ __align__(16) float sV[CH][128];
    __shared__ float sO[CH][129];

    const __half* vp = g_kv + ((size_t)b * C2 + C + h * CH) * HW + n0;
    const float* ap = g_attn + (size_t)(b * NH + h) * (CH * CH);

    for (int idx = tid; idx < CH * CH; idx += 256)
        sA[idx / CH][idx % CH] = ap[idx];
#pragma unroll
    for (int e = 0; e < 3; e++) {
        int idx = tid + e * 256;
        int d = idx >> 4, g = idx & 15;
        uint4 v = ((const uint4*)(vp + (size_t)d * HW))[g];
        const __half* hv = (const __half*)&v;
#pragma unroll
        for (int j = 0; j < 8; j++)
            sV[d][g * 8 + j] = __half2float(hv[j]);
    }
    __syncthreads();

    float4 acc[6];
#pragma unroll
    for (int i = 0; i < 6; i++) acc[i] = make_float4(0.f, 0.f, 0.f, 0.f);

    for (int d = 0; d < CH; d++) {
        float4 vv = ((const float4*)(&sV[d][0]))[tx];
#pragma unroll
        for (int i = 0; i < 6; i++) {
            float a = sA[ty * 6 + i][d];
            acc[i].x += a * vv.x; acc[i].y += a * vv.y;
            acc[i].z += a * vv.z; acc[i].w += a * vv.w;
        }
    }

#pragma unroll
    for (int i = 0; i < 6; i++) {
        float* so = &sO[ty * 6 + i][tx * 4];
        so[0] = acc[i].x; so[1] = acc[i].y; so[2] = acc[i].z; so[3] = acc[i].w;
    }
    __syncthreads();

    uint32_t* xp = (uint32_t*)g_xta;
    for (int idx = tid; idx < 128 * 24; idx += 256) {
        int p = idx / 24, u = idx - p * 24;
        int c0 = u * 2;
        __half2 hv = __half2(__float2half(sO[c0][p]), __float2half(sO[c0 + 1][p]));
        xp[(size_t)(b * HW + n0 + p) * 96 + h * 24 + u] = *(uint32_t*)&hv;
    }
}

// ---------------- launcher ----------------------------------------------------
extern "C" void kernel_launch(void* const* d_in, const int* in_sizes, int n_in,
                              void* d_out, int out_size)
{
    const float* x           = (const float*)d_in[0];
    const float* y           = (const float*)d_in[1];
    const float* w_qkv       = (const float*)d_in[2];
    const float* w_qkv_dw    = (const float*)d_in[3];
    const float* w_query     = (const float*)d_in[4];
    const float* w_query_dw  = (const float*)d_in[5];
    const float* w_proj      = (const float*)d_in[6];
    const float* temperature = (const float*)d_in[7];

    __half *t1, *kv, *t2, *q, *xta, *xtb, *w1, *w2, *w3;
    cudaGetSymbolAddress((void**)&t1,  g_t1);
    cudaGetSymbolAddress((void**)&kv,  g_kv);
    cudaGetSymbolAddress((void**)&t2,  g_t2);
    cudaGetSymbolAddress((void**)&q,   g_q);
    cudaGetSymbolAddress((void**)&xta, g_xta);
    cudaGetSymbolAddress((void**)&xtb, g_xtb);
    cudaGetSymbolAddress((void**)&w1,  g_w1);
    cudaGetSymbolAddress((void**)&w2,  g_w2);
    cudaGetSymbolAddress((void**)&w3,  g_w3);

    static int smem_set = 0;
    if (!smem_set) {
        cudaFuncSetAttribute(gemm12_kernel,
                             cudaFuncAttributeMaxDynamicSharedMemorySize, GSM_TOTAL);
        cudaFuncSetAttribute(gemm3_kernel,
                             cudaFuncAttributeMaxDynamicSharedMemorySize, GSM_TOTAL);
        smem_set = 1;
    }

    // weight fp16 convert (tiny)
    prep_w_kernel<<<384, 192>>>(w_qkv,   w1);
    prep_w_kernel<<<192, 192>>>(w_query, w2);
    prep_w_kernel<<<192, 192>>>(w_proj,  w3);

    // activation fp16 transposes
    split_transpose_kernel<<<dim3(HW / 64, B), 256>>>(x, xta);
    split_transpose_kernel<<<dim3(HW / 64, B), 256>>>(y, xtb);

    // conv1 + conv2 merged (y: 0,1 = conv1 cout blocks; 2 = conv2)
    gemm12_kernel<<<dim3(HW / (TPT * 128), 3, B), 256, GSM_TOTAL>>>();

    // depthwise 3x3 (fp16 in/out)
    dwconv3x3_kernel<<<dim3(H / 8, C2, B), 128>>>(t1, w_qkv_dw, kv, C2);
    dwconv3x3_kernel<<<dim3(H / 8, C, B), 128>>>(t2, w_query_dw, q, C);

    // attention
    gram_kernel<<<dim3(NCHUNK, NH, B), 256>>>();
    reduce_softmax_kernel<<<B * NH, 256>>>(temperature);
    attnv_split_kernel<<<dim3(HW / 128, NH, B), 256>>>();  // writes xta (fp16)

    // conv3: att -> out (fp32 to d_out)
    gemm3_kernel<<<dim3(HW / (TPT * 128), 1, B), 256, GSM_TOTAL>>>((float*)d_out);
}